// round 10
// baseline (speedup 1.0000x reference)
#include <cuda_runtime.h>
#include <cuda_bf16.h>
#include <math.h>

#define BB 32
#define FF 128
#define HH 256
#define NPTS 2048
#define SD 3
#define NE 262144
#define NN (BB*NPTS)      // 65536
#define TE 16
#define R0 (BB + NPTS)

// GEMM tiling
#define BM 128
#define BN 64
#define BK 32
#define KPAD 40

// ---------------- scratch (device globals; no allocation allowed) ----------
__device__ float g_h0[BB*HH];
__device__ float g_meand[NPTS];
__device__ float g_g[NPTS*HH];
__device__ float g_PQ[(size_t)NN*512];      // 128 MB: [P | Q] layer 1
__device__ float g_P0[R0*HH];
__device__ float g_Q0[R0*HH];
__device__ float g_U0[R0*HH];
__device__ float g_pos[NN*SD];
__device__ float g_dpos[NN*SD];

// CSR by dst
__device__ int g_deg[NN];
__device__ int g_off[NN+1];
__device__ int g_cur[NN];
__device__ int g_csr[NE];

// bf16 hi/lo activations (A operands)
__device__ __nv_bfloat16 g_h_hi[NN*HH], g_h_lo[NN*HH];
__device__ __nv_bfloat16 g_agg_hi[NN*HH], g_agg_lo[NN*HH];

// pre-split transposed weights (bf16 hi/lo), layout [N][K]
__device__ __nv_bfloat16 g_Bpq_hi[512*256], g_Bpq_lo[512*256];
__device__ __nv_bfloat16 g_Bu1_hi[256*512], g_Bu1_lo[256*512];
__device__ __nv_bfloat16 g_Bu0_hi[256*256], g_Bu0_lo[256*256];

// ---------------- helpers ----------------------------------------------------
__device__ __forceinline__ unsigned pack_bf2(__nv_bfloat16 a, __nv_bfloat16 b) {
    return (unsigned)__bfloat16_as_ushort(a) | ((unsigned)__bfloat16_as_ushort(b) << 16);
}
__device__ __forceinline__ void mma16816(float* c, unsigned a0, unsigned a1,
                                         unsigned a2, unsigned a3,
                                         unsigned b0, unsigned b1) {
    asm volatile(
        "mma.sync.aligned.m16n8k16.row.col.f32.bf16.bf16.f32 "
        "{%0,%1,%2,%3}, {%4,%5,%6,%7}, {%8,%9}, {%0,%1,%2,%3};\n"
        : "+f"(c[0]), "+f"(c[1]), "+f"(c[2]), "+f"(c[3])
        : "r"(a0), "r"(a1), "r"(a2), "r"(a3), "r"(b0), "r"(b1));
}
__device__ __forceinline__ void ldsm_x4(unsigned& r0, unsigned& r1, unsigned& r2,
                                        unsigned& r3, const __nv_bfloat16* p) {
    unsigned addr = (unsigned)__cvta_generic_to_shared(p);
    asm volatile("ldmatrix.sync.aligned.m8n8.x4.shared.b16 {%0,%1,%2,%3}, [%4];"
                 : "=r"(r0), "=r"(r1), "=r"(r2), "=r"(r3) : "r"(addr));
}

// GEMM mainloop: C[128x64], A = bf16 hi/lo (two K segments), B pre-split bf16 [N][K]
__device__ __forceinline__ void gemm_tile_bf16(
    const __nv_bfloat16* __restrict__ A0h, const __nv_bfloat16* __restrict__ A0l,
    const __nv_bfloat16* __restrict__ A1h, const __nv_bfloat16* __restrict__ A1l,
    int kSplit, int Ktot,
    const __nv_bfloat16* __restrict__ BTh, const __nv_bfloat16* __restrict__ BTl,
    int m0, int n0,
    __nv_bfloat16* sAh, __nv_bfloat16* sAl, __nv_bfloat16* sBh, __nv_bfloat16* sBl,
    float acc[2][4][4])
{
    int tid  = threadIdx.x;
    int lane = tid & 31, warp = tid >> 5;
    int wM = warp >> 1, wN = warp & 1;

    for (int k0 = 0; k0 < Ktot; k0 += BK) {
        const __nv_bfloat16 *Ah, *Al; int acol;
        if (k0 < kSplit) { Ah = A0h; Al = A0l; acol = k0; }
        else             { Ah = A1h; Al = A1l; acol = k0 - kSplit; }
        for (int i = tid; i < BM*8; i += 256) {
            int row = i >> 3, c4 = (i & 7) * 4;
            size_t go = (size_t)(m0 + row)*HH + acol + c4;
            int so = row*KPAD + c4;
            *(uint2*)(sAh + so) = *(const uint2*)(Ah + go);
            *(uint2*)(sAl + so) = *(const uint2*)(Al + go);
        }
        for (int i = tid; i < BN*8; i += 256) {
            int n = i >> 3, c4 = (i & 7) * 4;
            size_t go = (size_t)(n0 + n)*Ktot + k0 + c4;
            int so = n*KPAD + c4;
            *(uint2*)(sBh + so) = *(const uint2*)(BTh + go);
            *(uint2*)(sBl + so) = *(const uint2*)(BTl + go);
        }
        __syncthreads();

        #pragma unroll
        for (int ks = 0; ks < BK; ks += 16) {
            unsigned ah[2][4], al[2][4];
            #pragma unroll
            for (int fm = 0; fm < 2; fm++) {
                int arow = wM*32 + fm*16 + (lane & 15);
                int acol2 = ks + (lane >> 4) * 8;
                ldsm_x4(ah[fm][0], ah[fm][1], ah[fm][2], ah[fm][3], sAh + arow*KPAD + acol2);
                ldsm_x4(al[fm][0], al[fm][1], al[fm][2], al[fm][3], sAl + arow*KPAD + acol2);
            }
            unsigned bh[4][2], bl[4][2];
            #pragma unroll
            for (int fnp = 0; fnp < 2; fnp++) {
                int brow = wN*32 + fnp*16 + (lane & 7) + ((lane >> 4) << 3);
                int bcol = ks + ((lane >> 3) & 1) * 8;
                ldsm_x4(bh[fnp*2][0], bh[fnp*2][1], bh[fnp*2+1][0], bh[fnp*2+1][1],
                        sBh + brow*KPAD + bcol);
                ldsm_x4(bl[fnp*2][0], bl[fnp*2][1], bl[fnp*2+1][0], bl[fnp*2+1][1],
                        sBl + brow*KPAD + bcol);
            }
            #pragma unroll
            for (int fn = 0; fn < 4; fn++) {
                #pragma unroll
                for (int fm = 0; fm < 2; fm++) {
                    mma16816(acc[fm][fn], ah[fm][0], ah[fm][1], ah[fm][2], ah[fm][3],
                             bh[fn][0], bh[fn][1]);
                    mma16816(acc[fm][fn], ah[fm][0], ah[fm][1], ah[fm][2], ah[fm][3],
                             bl[fn][0], bl[fn][1]);
                    mma16816(acc[fm][fn], al[fm][0], al[fm][1], al[fm][2], al[fm][3],
                             bh[fn][0], bh[fn][1]);
                }
            }
        }
        __syncthreads();
    }
}

// ---------------- weight prep (split + transpose to [N][K]) -----------------
__global__ void k_prep_pq(const float* __restrict__ Wm1)
{
    int idx = blockIdx.x*256 + threadIdx.x;
    int k = idx >> 9, n = idx & 511;
    float v = (n < 256) ? Wm1[k*HH + n] : Wm1[(256 + k)*HH + (n - 256)];
    __nv_bfloat16 h = __float2bfloat16(v);
    g_Bpq_hi[n*256 + k] = h;
    g_Bpq_lo[n*256 + k] = __float2bfloat16(v - __bfloat162float(h));
}
__global__ void k_prep_u1(const float* __restrict__ Wu1)
{
    int idx = blockIdx.x*256 + threadIdx.x;
    int k = idx >> 8, n = idx & 255;
    float v = Wu1[k*HH + n];
    __nv_bfloat16 h = __float2bfloat16(v);
    g_Bu1_hi[n*512 + k] = h;
    g_Bu1_lo[n*512 + k] = __float2bfloat16(v - __bfloat162float(h));
}
__global__ void k_prep_u0(const float* __restrict__ Wu0)
{
    int idx = blockIdx.x*256 + threadIdx.x;
    int k = idx >> 8, n = idx & 255;
    float v = Wu0[(256 + k)*HH + n];
    __nv_bfloat16 h = __float2bfloat16(v);
    g_Bu0_hi[n*256 + k] = h;
    g_Bu0_lo[n*256 + k] = __float2bfloat16(v - __bfloat162float(h));
}

// ---------------- CSR build --------------------------------------------------
__global__ void k_degzero()
{
    int i = blockIdx.x*256 + threadIdx.x;
    if (i < NN) g_deg[i] = 0;
}
__global__ void k_hist(const int* __restrict__ dst)
{
    int e = blockIdx.x*256 + threadIdx.x;
    if (e < NE) atomicAdd(&g_deg[dst[e]], 1);
}
__global__ void k_scan()   // 1 block, 1024 threads; 64 elems/thread
{
    __shared__ int ps[1024];
    int t = threadIdx.x;
    int base = t * 64;
    int s = 0;
    for (int i = 0; i < 64; i++) s += g_deg[base + i];
    ps[t] = s;
    __syncthreads();
    for (int off = 1; off < 1024; off <<= 1) {
        int v = (t >= off) ? ps[t - off] : 0;
        __syncthreads();
        ps[t] += v;
        __syncthreads();
    }
    int run = (t == 0) ? 0 : ps[t - 1];
    for (int i = 0; i < 64; i++) {
        g_off[base + i] = run;
        g_cur[base + i] = run;
        run += g_deg[base + i];
    }
    if (t == 1023) g_off[NN] = run;
}
__global__ void k_scatter(const int* __restrict__ src, const int* __restrict__ dst)
{
    int e = blockIdx.x*256 + threadIdx.x;
    if (e < NE) {
        int p = atomicAdd(&g_cur[dst[e]], 1);
        g_csr[p] = src[e];
    }
}

// ---------------- front-end --------------------------------------------------
__global__ void k_h0(const float* __restrict__ x, const float* __restrict__ W,
                     const float* __restrict__ b)
{
    int bi = blockIdx.x, j = threadIdx.x;
    __shared__ float xr[FF];
    if (j < FF) xr[j] = x[bi*FF + j];
    __syncthreads();
    float acc = b[j];
    #pragma unroll 4
    for (int k = 0; k < FF; k++) acc = fmaf(xr[k], W[k*HH + j], acc);
    g_h0[bi*HH + j] = acc;
}

__global__ void k_meand(const float* __restrict__ P)
{
    int i = blockIdx.x;
    float px = P[i*3+0], py = P[i*3+1], pz = P[i*3+2];
    float s = 0.f;
    for (int j = threadIdx.x; j < NPTS; j += 256) {
        if (j == i) continue;
        float dx = px - P[j*3+0], dy = py - P[j*3+1], dz = pz - P[j*3+2];
        s += sqrtf(dx*dx + dy*dy + dz*dz);
    }
    __shared__ float red[256];
    red[threadIdx.x] = s;
    __syncthreads();
    for (int st = 128; st > 0; st >>= 1) {
        if (threadIdx.x < st) red[threadIdx.x] += red[threadIdx.x + st];
        __syncthreads();
    }
    if (threadIdx.x == 0) g_meand[i] = red[0] / (float)(NPTS - 1);
}

__global__ void k_geo(const float* __restrict__ Wg1, const float* __restrict__ bg1,
                      const float* __restrict__ Wg2, const float* __restrict__ bg2)
{
    int i = blockIdx.x, j = threadIdx.x;
    __shared__ float t[FF];
    float m = g_meand[i];
    if (j < FF) {
        float ws = Wg1[j] + Wg1[FF + j] + Wg1[2*FF + j];
        t[j] = fmaxf(fmaf(m, ws, bg1[j]), 0.f);
    }
    __syncthreads();
    float acc = bg2[j];
    #pragma unroll 4
    for (int k = 0; k < FF; k++) acc = fmaf(t[k], Wg2[k*HH + j], acc);
    g_g[i*HH + j] = acc;
}

__global__ void k_posinit(const float* __restrict__ P)
{
    int i = blockIdx.x * blockDim.x + threadIdx.x;
    if (i < NN*SD) {
        int bn = i / 3, c = i - bn*3;
        int n = bn & (NPTS - 1);
        g_pos[i] = P[n*3 + c];
    }
}

__global__ void k_posupd()
{
    int i = blockIdx.x * blockDim.x + threadIdx.x;
    if (i < NN*SD) g_pos[i] += g_dpos[i] * 0.25f;
}

__global__ void k_oinit(const float* __restrict__ bo, float* __restrict__ out)
{
    int i = blockIdx.x * blockDim.x + threadIdx.x;
    if (i < NN) out[i] = bo[0];
}

// ------- layer-0 low-rank tables ---------------------------------------------
__global__ void __launch_bounds__(256) pq0_kernel(
    const float* __restrict__ Wm, const float* __restrict__ Wu)
{
    __shared__ __align__(16) float sm[TE * HH];
    int tid = threadIdx.x;
    int r0 = blockIdx.x * TE;

    #pragma unroll 4
    for (int e = 0; e < TE; e++) {
        int r = r0 + e;
        const float* row = (r < BB) ? (g_h0 + r*HH) : (g_g + (r - BB)*HH);
        sm[e*HH + tid] = row[tid];
    }
    __syncthreads();

    float accP[TE], accQ[TE], accU[TE];
    #pragma unroll
    for (int e = 0; e < TE; e++) { accP[e] = 0.f; accQ[e] = 0.f; accU[e] = 0.f; }

    const float* wt = Wm + tid;
    const float* wq = Wm + (size_t)HH*HH + tid;
    const float* wu = Wu + tid;
    for (int k4 = 0; k4 < HH/4; k4++) {
        float t0 = wt[(4*k4+0)*HH], t1 = wt[(4*k4+1)*HH];
        float t2 = wt[(4*k4+2)*HH], t3 = wt[(4*k4+3)*HH];
        float q0 = wq[(4*k4+0)*HH], q1 = wq[(4*k4+1)*HH];
        float q2 = wq[(4*k4+2)*HH], q3 = wq[(4*k4+3)*HH];
        float u0 = wu[(4*k4+0)*HH], u1 = wu[(4*k4+1)*HH];
        float u2 = wu[(4*k4+2)*HH], u3 = wu[(4*k4+3)*HH];
        #pragma unroll
        for (int e = 0; e < TE; e++) {
            float4 f = *(const float4*)(sm + e*HH + 4*k4);
            accP[e] = fmaf(f.w, t3, fmaf(f.z, t2, fmaf(f.y, t1, fmaf(f.x, t0, accP[e]))));
            accQ[e] = fmaf(f.w, q3, fmaf(f.z, q2, fmaf(f.y, q1, fmaf(f.x, q0, accQ[e]))));
            accU[e] = fmaf(f.w, u3, fmaf(f.z, u2, fmaf(f.y, u1, fmaf(f.x, u0, accU[e]))));
        }
    }
    #pragma unroll
    for (int e = 0; e < TE; e++) {
        g_P0[(r0 + e)*HH + tid] = accP[e];
        g_Q0[(r0 + e)*HH + tid] = accQ[e];
        g_U0[(r0 + e)*HH + tid] = accU[e];
    }
}

// ---------------- layer-0 gather aggregation (block = dst node) -------------
// agg[d] = sum_e relu(P0[src] + Q0[d] + d_e*wd + bm); dpos[d] computed in-block
__global__ void __launch_bounds__(256) agg0_gather(
    const float* __restrict__ Wm, const float* __restrict__ bm,
    const float* __restrict__ Wp)
{
    __shared__ float spart[8];
    int d = blockIdx.x, tid = threadIdx.x;
    int lo = g_off[d], hi = g_off[d+1];
    float pdx = g_pos[d*3+0], pdy = g_pos[d*3+1], pdz = g_pos[d*3+2];
    float wd = Wm[(size_t)512*HH + tid];
    float bj = bm[tid];
    float wp = Wp[tid];
    int bt = d >> 11, nt = d & (NPTS-1);
    float q = g_Q0[bt*HH + tid] + g_Q0[(BB + nt)*HH + tid];
    float a = 0.f, cx = 0.f, cy = 0.f, cz = 0.f;
    int lane = tid & 31, wrp = tid >> 5;

    for (int j = lo; j < hi; j++) {
        int s = g_csr[j];
        float dx = g_pos[s*3+0] - pdx;
        float dy = g_pos[s*3+1] - pdy;
        float dz = g_pos[s*3+2] - pdz;
        float sd = sqrtf(dx*dx + dy*dy + dz*dz + 1e-12f);
        int bs = s >> 11, ns = s & (NPTS-1);
        float m = g_P0[bs*HH + tid] + g_P0[(BB + ns)*HH + tid] + q;
        m = fmaxf(fmaf(sd, wd, m) + bj, 0.f);
        a += m;
        float v = m * wp;
        v += __shfl_xor_sync(0xffffffffu, v, 16);
        v += __shfl_xor_sync(0xffffffffu, v, 8);
        v += __shfl_xor_sync(0xffffffffu, v, 4);
        v += __shfl_xor_sync(0xffffffffu, v, 2);
        v += __shfl_xor_sync(0xffffffffu, v, 1);
        if (lane == 0) spart[wrp] = v;
        __syncthreads();
        if (tid == 0) {
            float coef = spart[0]+spart[1]+spart[2]+spart[3]
                       + spart[4]+spart[5]+spart[6]+spart[7];
            cx = fmaf(-dx, coef, cx);      // (pos[dst]-pos[src]) = -dvec
            cy = fmaf(-dy, coef, cy);
            cz = fmaf(-dz, coef, cz);
        }
        __syncthreads();
    }
    __nv_bfloat16 h = __float2bfloat16(a);
    g_agg_hi[(size_t)d*HH + tid] = h;
    g_agg_lo[(size_t)d*HH + tid] = __float2bfloat16(a - __bfloat162float(h));
    if (tid == 0) {
        g_dpos[d*3+0] = cx; g_dpos[d*3+1] = cy; g_dpos[d*3+2] = cz;
    }
}

// ---------------- layer-1 gather aggregation (no dpos) ----------------------
__global__ void __launch_bounds__(256) agg1_gather(
    const float* __restrict__ Wm, const float* __restrict__ bm)
{
    int d = blockIdx.x, tid = threadIdx.x;
    int lo = g_off[d], hi = g_off[d+1];
    float pdx = g_pos[d*3+0], pdy = g_pos[d*3+1], pdz = g_pos[d*3+2];
    float wd = Wm[(size_t)512*HH + tid];
    float bj = bm[tid];
    float q = g_PQ[(size_t)d*512 + 256 + tid];
    float a = 0.f;

    for (int j = lo; j < hi; j++) {
        int s = g_csr[j];
        float dx = g_pos[s*3+0] - pdx;
        float dy = g_pos[s*3+1] - pdy;
        float dz = g_pos[s*3+2] - pdz;
        float sd = sqrtf(dx*dx + dy*dy + dz*dz + 1e-12f);
        float m = fmaf(sd, wd, g_PQ[(size_t)s*512 + tid] + q) + bj;
        a += fmaxf(m, 0.f);
    }
    __nv_bfloat16 h = __float2bfloat16(a);
    g_agg_hi[(size_t)d*HH + tid] = h;
    g_agg_lo[(size_t)d*HH + tid] = __float2bfloat16(a - __bfloat162float(h));
}

// ---------------- upd0 (MMA): h = h0[b]+g[n] + relu(agg@Wu_bot + U0 + bu) ---
__global__ void __launch_bounds__(256) upd0_mma(const float* __restrict__ bu)
{
    __shared__ __align__(16) __nv_bfloat16 sAh[BM*KPAD], sAl[BM*KPAD];
    __shared__ __align__(16) __nv_bfloat16 sBh[BN*KPAD], sBl[BN*KPAD];
    float acc[2][4][4];
    #pragma unroll
    for (int a = 0; a < 2; a++)
        #pragma unroll
        for (int b = 0; b < 4; b++)
            #pragma unroll
            for (int c = 0; c < 4; c++) acc[a][b][c] = 0.f;

    int m0 = blockIdx.x * BM;
    int n0 = blockIdx.y * BN;
    gemm_tile_bf16(g_agg_hi, g_agg_lo, g_agg_hi, g_agg_lo, HH, HH,
                   g_Bu0_hi, g_Bu0_lo, m0, n0, sAh, sAl, sBh, sBl, acc);

    int lane = threadIdx.x & 31, warp = threadIdx.x >> 5;
    int g = lane >> 2, tg = lane & 3;
    int wM = warp >> 1, wN = warp & 1;
    int b = m0 >> 11;
    #pragma unroll
    for (int fm = 0; fm < 2; fm++) {
        #pragma unroll
        for (int fn = 0; fn < 4; fn++) {
            int c = n0 + wN*32 + fn*8 + tg*2;
            float b0 = bu[c], b1 = bu[c+1];
            #pragma unroll
            for (int rr = 0; rr < 2; rr++) {
                int m = m0 + wM*32 + fm*16 + g + rr*8;
                int n = m & (NPTS-1);
                float base0 = g_h0[b*HH + c]   + g_g[n*HH + c];
                float base1 = g_h0[b*HH + c+1] + g_g[n*HH + c+1];
                float ua0 = acc[fm][fn][rr*2+0] + g_U0[b*HH + c]   + g_U0[(BB+n)*HH + c]   + b0;
                float ua1 = acc[fm][fn][rr*2+1] + g_U0[b*HH + c+1] + g_U0[(BB+n)*HH + c+1] + b1;
                float o0 = base0 + fmaxf(ua0, 0.f);
                float o1 = base1 + fmaxf(ua1, 0.f);
                __nv_bfloat16 h0_ = __float2bfloat16(o0);
                __nv_bfloat16 h1_ = __float2bfloat16(o1);
                *(unsigned*)(g_h_hi + (size_t)m*HH + c) = pack_bf2(h0_, h1_);
                *(unsigned*)(g_h_lo + (size_t)m*HH + c) =
                    pack_bf2(__float2bfloat16(o0 - __bfloat162float(h0_)),
                             __float2bfloat16(o1 - __bfloat162float(h1_)));
            }
        }
    }
}

// ---------------- pq1 (MMA): g_PQ = h @ [Wm_top | Wm_mid] -------------------
__global__ void __launch_bounds__(256) pq1_mma()
{
    __shared__ __align__(16) __nv_bfloat16 sAh[BM*KPAD], sAl[BM*KPAD];
    __shared__ __align__(16) __nv_bfloat16 sBh[BN*KPAD], sBl[BN*KPAD];
    float acc[2][4][4];
    #pragma unroll
    for (int a = 0; a < 2; a++)
        #pragma unroll
        for (int b = 0; b < 4; b++)
            #pragma unroll
            for (int c = 0; c < 4; c++) acc[a][b][c] = 0.f;

    int m0 = blockIdx.x * BM;
    int n0 = blockIdx.y * BN;
    gemm_tile_bf16(g_h_hi, g_h_lo, g_h_hi, g_h_lo, HH, HH,
                   g_Bpq_hi, g_Bpq_lo, m0, n0, sAh, sAl, sBh, sBl, acc);

    int lane = threadIdx.x & 31, warp = threadIdx.x >> 5;
    int g = lane >> 2, tg = lane & 3;
    int wM = warp >> 1, wN = warp & 1;
    #pragma unroll
    for (int fm = 0; fm < 2; fm++) {
        #pragma unroll
        for (int fn = 0; fn < 4; fn++) {
            int c = n0 + wN*32 + fn*8 + tg*2;
            #pragma unroll
            for (int rr = 0; rr < 2; rr++) {
                int m = m0 + wM*32 + fm*16 + g + rr*8;
                float2 o; o.x = acc[fm][fn][rr*2+0]; o.y = acc[fm][fn][rr*2+1];
                *(float2*)(g_PQ + (size_t)m*512 + c) = o;
            }
        }
    }
}

// ---------------- upd1 (MMA) + fused output ---------------------------------
__global__ void __launch_bounds__(256) upd1_mma(
    const float* __restrict__ bu, const float* __restrict__ Wo,
    float* __restrict__ out)
{
    __shared__ __align__(16) __nv_bfloat16 sAh[BM*KPAD], sAl[BM*KPAD];
    __shared__ __align__(16) __nv_bfloat16 sBh[BN*KPAD], sBl[BN*KPAD];
    float acc[2][4][4];
    #pragma unroll
    for (int a = 0; a < 2; a++)
        #pragma unroll
        for (int b = 0; b < 4; b++)
            #pragma unroll
            for (int c = 0; c < 4; c++) acc[a][b][c] = 0.f;

    int m0 = blockIdx.x * BM;
    int n0 = blockIdx.y * BN;
    gemm_tile_bf16(g_h_hi, g_h_lo, g_agg_hi, g_agg_lo, HH, 2*HH,
                   g_Bu1_hi, g_Bu1_lo, m0, n0, sAh, sAl, sBh, sBl, acc);

    int lane = threadIdx.x & 31, warp = threadIdx.x >> 5;
    int g = lane >> 2, tg = lane & 3;
    int wM = warp >> 1, wN = warp & 1;
    #pragma unroll
    for (int fm = 0; fm < 2; fm++) {
        #pragma unroll
        for (int rr = 0; rr < 2; rr++) {
            int m = m0 + wM*32 + fm*16 + g + rr*8;
            float rowsum = 0.f;
            #pragma unroll
            for (int fn = 0; fn < 4; fn++) {
                int c = n0 + wN*32 + fn*8 + tg*2;
                unsigned hh = *(const unsigned*)(g_h_hi + (size_t)m*HH + c);
                unsigned hl = *(const unsigned*)(g_h_lo + (size_t)m*HH + c);
                float hold0 = __bfloat162float(__ushort_as_bfloat16((unsigned short)(hh & 0xffff)))
                            + __bfloat162float(__ushort_as_bfloat16((unsigned short)(hl & 0xffff)));
                float hold1 = __bfloat162float(__ushort_as_bfloat16((unsigned short)(hh >> 16)))
                            + __bfloat162float(__ushort_as_bfloat16((unsigned short)(hl >> 16)));
                float o0 = hold0 + fmaxf(acc[fm][fn][rr*2+0] + bu[c], 0.f);
                float o1 = hold1 + fmaxf(acc[fm][fn][rr*2+1] + bu[c+1], 0.f);
                rowsum = fmaf(o0, Wo[c], rowsum);
                rowsum = fmaf(o1, Wo[c+1], rowsum);
            }
            rowsum += __shfl_xor_sync(0xffffffffu, rowsum, 1);
            rowsum += __shfl_xor_sync(0xffffffffu, rowsum, 2);
            if (tg == 0) atomicAdd(out + m, rowsum);
        }
    }
}

// ---------------------------------------------------------------------------
extern "C" void kernel_launch(void* const* d_in, const int* in_sizes, int n_in,
                              void* d_out, int out_size)
{
    const float* x         = (const float*)d_in[0];
    const float* positions = (const float*)d_in[1];
    const float* W_in      = (const float*)d_in[2];
    const float* b_in      = (const float*)d_in[3];
    const float* Wg1       = (const float*)d_in[4];
    const float* bg1       = (const float*)d_in[5];
    const float* Wg2       = (const float*)d_in[6];
    const float* bg2       = (const float*)d_in[7];
    const float* Wm        = (const float*)d_in[8];
    const float* bm        = (const float*)d_in[9];
    const float* Wu        = (const float*)d_in[10];
    const float* bu        = (const float*)d_in[11];
    const float* Wp        = (const float*)d_in[12];
    const float* W_out     = (const float*)d_in[13];
    const float* b_out     = (const float*)d_in[14];
    const int*   edge      = (const int*)d_in[15];
    float* out = (float*)d_out;

    const int* srcp = edge;
    const int* dstp = edge + NE;
    const float* Wm1 = Wm + (size_t)513*HH;
    const float* Wu1 = Wu + (size_t)512*HH;

    // front-end + weight prep + CSR
    k_h0<<<BB, 256>>>(x, W_in, b_in);
    k_meand<<<NPTS, 256>>>(positions);
    k_geo<<<NPTS, 256>>>(Wg1, bg1, Wg2, bg2);
    k_posinit<<<(NN*SD + 255)/256, 256>>>(positions);
    k_prep_pq<<<512, 256>>>(Wm1);
    k_prep_u1<<<512, 256>>>(Wu1);
    k_prep_u0<<<256, 256>>>(Wu);
    k_degzero<<<NN/256, 256>>>();
    k_hist<<<NE/256, 256>>>(dstp);
    k_scan<<<1, 1024>>>();
    k_scatter<<<NE/256, 256>>>(srcp, dstp);

    // ---- layer 0 ----
    pq0_kernel<<<R0/TE, 256>>>(Wm, Wu);
    agg0_gather<<<NN, 256>>>(Wm, bm, Wp);
    upd0_mma<<<dim3(NN/BM, HH/BN), 256>>>(bu);
    k_posupd<<<(NN*SD + 255)/256, 256>>>();

    // ---- layer 1 ----
    pq1_mma<<<dim3(NN/BM, 512/BN), 256>>>();
    agg1_gather<<<NN, 256>>>(Wm1, bm + HH);
    k_oinit<<<NN/256, 256>>>(b_out, out);
    upd1_mma<<<dim3(NN/BM, HH/BN), 256>>>(bu + HH, W_out, out);
}

// round 11
// speedup vs baseline: 1.1535x; 1.1535x over previous
#include <cuda_runtime.h>
#include <cuda_bf16.h>
#include <math.h>

#define BB 32
#define FF 128
#define HH 256
#define NPTS 2048
#define SD 3
#define NE 262144
#define NN (BB*NPTS)      // 65536
#define TE 16
#define R0 (BB + NPTS)

// GEMM tiling
#define BM 128
#define BN 128
#define BK 32
#define KPAD 40

// ---------------- scratch (device globals; no allocation allowed) ----------
__device__ float g_h0[BB*HH];
__device__ float g_meand[NPTS];
__device__ float g_g[NPTS*HH];
__device__ float g_PQ[(size_t)NN*512];      // 128 MB: [P | Q] layer 1
__device__ float g_P0[R0*HH];
__device__ float g_Q0[R0*HH];
__device__ float g_U0[R0*HH];
__device__ float g_pos[NN*SD];
__device__ float g_dpos[NN*SD];

// CSR by dst
__device__ int g_deg[NN];
__device__ int g_off[NN+1];
__device__ int g_cur[NN];
__device__ int g_csr[NE];

// bf16 hi/lo activations (A operands)
__device__ __nv_bfloat16 g_h_hi[NN*HH], g_h_lo[NN*HH];
__device__ __nv_bfloat16 g_agg_hi[NN*HH], g_agg_lo[NN*HH];

// pre-split transposed weights (bf16 hi/lo), layout [N][K]
__device__ __nv_bfloat16 g_Bpq_hi[512*256], g_Bpq_lo[512*256];
__device__ __nv_bfloat16 g_Bu1_hi[256*512], g_Bu1_lo[256*512];
__device__ __nv_bfloat16 g_Bu0_hi[256*256], g_Bu0_lo[256*256];

// ---------------- helpers ----------------------------------------------------
__device__ __forceinline__ unsigned pack_bf2(__nv_bfloat16 a, __nv_bfloat16 b) {
    return (unsigned)__bfloat16_as_ushort(a) | ((unsigned)__bfloat16_as_ushort(b) << 16);
}
__device__ __forceinline__ void mma16816(float* c, unsigned a0, unsigned a1,
                                         unsigned a2, unsigned a3,
                                         unsigned b0, unsigned b1) {
    asm volatile(
        "mma.sync.aligned.m16n8k16.row.col.f32.bf16.bf16.f32 "
        "{%0,%1,%2,%3}, {%4,%5,%6,%7}, {%8,%9}, {%0,%1,%2,%3};\n"
        : "+f"(c[0]), "+f"(c[1]), "+f"(c[2]), "+f"(c[3])
        : "r"(a0), "r"(a1), "r"(a2), "r"(a3), "r"(b0), "r"(b1));
}
__device__ __forceinline__ void ldsm_x4(unsigned& r0, unsigned& r1, unsigned& r2,
                                        unsigned& r3, const __nv_bfloat16* p) {
    unsigned addr = (unsigned)__cvta_generic_to_shared(p);
    asm volatile("ldmatrix.sync.aligned.m8n8.x4.shared.b16 {%0,%1,%2,%3}, [%4];"
                 : "=r"(r0), "=r"(r1), "=r"(r2), "=r"(r3) : "r"(addr));
}
__device__ __forceinline__ void cp_async16(__nv_bfloat16* smem, const __nv_bfloat16* g) {
    unsigned s = (unsigned)__cvta_generic_to_shared(smem);
    asm volatile("cp.async.cg.shared.global [%0], [%1], 16;" :: "r"(s), "l"(g));
}

// GEMM mainloop: C[128x128], A = bf16 hi/lo (two K segments), B pre-split bf16 [N][K]
__device__ __forceinline__ void gemm_tile_bf16(
    const __nv_bfloat16* __restrict__ A0h, const __nv_bfloat16* __restrict__ A0l,
    const __nv_bfloat16* __restrict__ A1h, const __nv_bfloat16* __restrict__ A1l,
    int kSplit, int Ktot,
    const __nv_bfloat16* __restrict__ BTh, const __nv_bfloat16* __restrict__ BTl,
    int m0, int n0,
    __nv_bfloat16* sAh, __nv_bfloat16* sAl, __nv_bfloat16* sBh, __nv_bfloat16* sBl,
    float acc[2][8][4])
{
    int tid  = threadIdx.x;
    int lane = tid & 31, warp = tid >> 5;
    int wM = warp >> 1, wN = warp & 1;

    for (int k0 = 0; k0 < Ktot; k0 += BK) {
        const __nv_bfloat16 *Ah, *Al; int acol;
        if (k0 < kSplit) { Ah = A0h; Al = A0l; acol = k0; }
        else             { Ah = A1h; Al = A1l; acol = k0 - kSplit; }
        // A tile: 128 rows x 32 bf16, 16B cp.async chunks
        #pragma unroll
        for (int it = 0; it < 2; it++) {
            int i = tid + it*256;                 // over BM*4 = 512
            int row = i >> 2, c8 = (i & 3) * 8;
            size_t go = (size_t)(m0 + row)*HH + acol + c8;
            int so = row*KPAD + c8;
            cp_async16(sAh + so, Ah + go);
            cp_async16(sAl + so, Al + go);
        }
        // B tile: 128 rows x 32 bf16
        #pragma unroll
        for (int it = 0; it < 2; it++) {
            int i = tid + it*256;                 // over BN*4 = 512
            int n = i >> 2, c8 = (i & 3) * 8;
            size_t go = (size_t)(n0 + n)*Ktot + k0 + c8;
            int so = n*KPAD + c8;
            cp_async16(sBh + so, BTh + go);
            cp_async16(sBl + so, BTl + go);
        }
        asm volatile("cp.async.commit_group;");
        asm volatile("cp.async.wait_group 0;");
        __syncthreads();

        #pragma unroll
        for (int ks = 0; ks < BK; ks += 16) {
            unsigned ah[2][4], al[2][4];
            #pragma unroll
            for (int fm = 0; fm < 2; fm++) {
                int arow = wM*32 + fm*16 + (lane & 15);
                int acol2 = ks + (lane >> 4) * 8;
                ldsm_x4(ah[fm][0], ah[fm][1], ah[fm][2], ah[fm][3], sAh + arow*KPAD + acol2);
                ldsm_x4(al[fm][0], al[fm][1], al[fm][2], al[fm][3], sAl + arow*KPAD + acol2);
            }
            unsigned bh[8][2], bl[8][2];
            #pragma unroll
            for (int fnp = 0; fnp < 4; fnp++) {
                int brow = wN*64 + fnp*16 + (lane & 7) + ((lane >> 4) << 3);
                int bcol = ks + ((lane >> 3) & 1) * 8;
                ldsm_x4(bh[fnp*2][0], bh[fnp*2][1], bh[fnp*2+1][0], bh[fnp*2+1][1],
                        sBh + brow*KPAD + bcol);
                ldsm_x4(bl[fnp*2][0], bl[fnp*2][1], bl[fnp*2+1][0], bl[fnp*2+1][1],
                        sBl + brow*KPAD + bcol);
            }
            #pragma unroll
            for (int fn = 0; fn < 8; fn++) {
                #pragma unroll
                for (int fm = 0; fm < 2; fm++) {
                    mma16816(acc[fm][fn], ah[fm][0], ah[fm][1], ah[fm][2], ah[fm][3],
                             bh[fn][0], bh[fn][1]);
                    mma16816(acc[fm][fn], ah[fm][0], ah[fm][1], ah[fm][2], ah[fm][3],
                             bl[fn][0], bl[fn][1]);
                    mma16816(acc[fm][fn], al[fm][0], al[fm][1], al[fm][2], al[fm][3],
                             bh[fn][0], bh[fn][1]);
                }
            }
        }
        __syncthreads();
    }
}

// ---------------- weight prep (split + transpose to [N][K]) -----------------
__global__ void k_prep_pq(const float* __restrict__ Wm1)
{
    int idx = blockIdx.x*256 + threadIdx.x;
    int k = idx >> 9, n = idx & 511;
    float v = (n < 256) ? Wm1[k*HH + n] : Wm1[(256 + k)*HH + (n - 256)];
    __nv_bfloat16 h = __float2bfloat16(v);
    g_Bpq_hi[n*256 + k] = h;
    g_Bpq_lo[n*256 + k] = __float2bfloat16(v - __bfloat162float(h));
}
__global__ void k_prep_u1(const float* __restrict__ Wu1)
{
    int idx = blockIdx.x*256 + threadIdx.x;
    int k = idx >> 8, n = idx & 255;
    float v = Wu1[k*HH + n];
    __nv_bfloat16 h = __float2bfloat16(v);
    g_Bu1_hi[n*512 + k] = h;
    g_Bu1_lo[n*512 + k] = __float2bfloat16(v - __bfloat162float(h));
}
__global__ void k_prep_u0(const float* __restrict__ Wu0)
{
    int idx = blockIdx.x*256 + threadIdx.x;
    int k = idx >> 8, n = idx & 255;
    float v = Wu0[(256 + k)*HH + n];
    __nv_bfloat16 h = __float2bfloat16(v);
    g_Bu0_hi[n*256 + k] = h;
    g_Bu0_lo[n*256 + k] = __float2bfloat16(v - __bfloat162float(h));
}

// ---------------- CSR build --------------------------------------------------
__global__ void k_degzero()
{
    int i = blockIdx.x*256 + threadIdx.x;
    if (i < NN) g_deg[i] = 0;
}
__global__ void k_hist(const int* __restrict__ dst)
{
    int e = blockIdx.x*256 + threadIdx.x;
    if (e < NE) atomicAdd(&g_deg[dst[e]], 1);
}
__global__ void k_scan()   // 1 block, 1024 threads; 64 elems/thread
{
    __shared__ int ps[1024];
    int t = threadIdx.x;
    int base = t * 64;
    int s = 0;
    for (int i = 0; i < 64; i++) s += g_deg[base + i];
    ps[t] = s;
    __syncthreads();
    for (int off = 1; off < 1024; off <<= 1) {
        int v = (t >= off) ? ps[t - off] : 0;
        __syncthreads();
        ps[t] += v;
        __syncthreads();
    }
    int run = (t == 0) ? 0 : ps[t - 1];
    for (int i = 0; i < 64; i++) {
        g_off[base + i] = run;
        g_cur[base + i] = run;
        run += g_deg[base + i];
    }
    if (t == 1023) g_off[NN] = run;
}
__global__ void k_scatter(const int* __restrict__ src, const int* __restrict__ dst)
{
    int e = blockIdx.x*256 + threadIdx.x;
    if (e < NE) {
        int p = atomicAdd(&g_cur[dst[e]], 1);
        g_csr[p] = src[e];
    }
}

// ---------------- front-end --------------------------------------------------
__global__ void k_h0(const float* __restrict__ x, const float* __restrict__ W,
                     const float* __restrict__ b)
{
    int bi = blockIdx.x, j = threadIdx.x;
    __shared__ float xr[FF];
    if (j < FF) xr[j] = x[bi*FF + j];
    __syncthreads();
    float acc = b[j];
    #pragma unroll 4
    for (int k = 0; k < FF; k++) acc = fmaf(xr[k], W[k*HH + j], acc);
    g_h0[bi*HH + j] = acc;
}

__global__ void k_meand(const float* __restrict__ P)
{
    int i = blockIdx.x;
    float px = P[i*3+0], py = P[i*3+1], pz = P[i*3+2];
    float s = 0.f;
    for (int j = threadIdx.x; j < NPTS; j += 256) {
        if (j == i) continue;
        float dx = px - P[j*3+0], dy = py - P[j*3+1], dz = pz - P[j*3+2];
        s += sqrtf(dx*dx + dy*dy + dz*dz);
    }
    __shared__ float red[256];
    red[threadIdx.x] = s;
    __syncthreads();
    for (int st = 128; st > 0; st >>= 1) {
        if (threadIdx.x < st) red[threadIdx.x] += red[threadIdx.x + st];
        __syncthreads();
    }
    if (threadIdx.x == 0) g_meand[i] = red[0] / (float)(NPTS - 1);
}

__global__ void k_geo(const float* __restrict__ Wg1, const float* __restrict__ bg1,
                      const float* __restrict__ Wg2, const float* __restrict__ bg2)
{
    int i = blockIdx.x, j = threadIdx.x;
    __shared__ float t[FF];
    float m = g_meand[i];
    if (j < FF) {
        float ws = Wg1[j] + Wg1[FF + j] + Wg1[2*FF + j];
        t[j] = fmaxf(fmaf(m, ws, bg1[j]), 0.f);
    }
    __syncthreads();
    float acc = bg2[j];
    #pragma unroll 4
    for (int k = 0; k < FF; k++) acc = fmaf(t[k], Wg2[k*HH + j], acc);
    g_g[i*HH + j] = acc;
}

__global__ void k_posinit(const float* __restrict__ P)
{
    int i = blockIdx.x * blockDim.x + threadIdx.x;
    if (i < NN*SD) {
        int bn = i / 3, c = i - bn*3;
        int n = bn & (NPTS - 1);
        g_pos[i] = P[n*3 + c];
    }
}

__global__ void k_posupd()
{
    int i = blockIdx.x * blockDim.x + threadIdx.x;
    if (i < NN*SD) g_pos[i] += g_dpos[i] * 0.25f;
}

__global__ void k_oinit(const float* __restrict__ bo, float* __restrict__ out)
{
    int i = blockIdx.x * blockDim.x + threadIdx.x;
    if (i < NN) out[i] = bo[0];
}

// ------- layer-0 low-rank tables ---------------------------------------------
__global__ void __launch_bounds__(256) pq0_kernel(
    const float* __restrict__ Wm, const float* __restrict__ Wu)
{
    __shared__ __align__(16) float sm[TE * HH];
    int tid = threadIdx.x;
    int r0 = blockIdx.x * TE;

    #pragma unroll 4
    for (int e = 0; e < TE; e++) {
        int r = r0 + e;
        const float* row = (r < BB) ? (g_h0 + r*HH) : (g_g + (r - BB)*HH);
        sm[e*HH + tid] = row[tid];
    }
    __syncthreads();

    float accP[TE], accQ[TE], accU[TE];
    #pragma unroll
    for (int e = 0; e < TE; e++) { accP[e] = 0.f; accQ[e] = 0.f; accU[e] = 0.f; }

    const float* wt = Wm + tid;
    const float* wq = Wm + (size_t)HH*HH + tid;
    const float* wu = Wu + tid;
    for (int k4 = 0; k4 < HH/4; k4++) {
        float t0 = wt[(4*k4+0)*HH], t1 = wt[(4*k4+1)*HH];
        float t2 = wt[(4*k4+2)*HH], t3 = wt[(4*k4+3)*HH];
        float q0 = wq[(4*k4+0)*HH], q1 = wq[(4*k4+1)*HH];
        float q2 = wq[(4*k4+2)*HH], q3 = wq[(4*k4+3)*HH];
        float u0 = wu[(4*k4+0)*HH], u1 = wu[(4*k4+1)*HH];
        float u2 = wu[(4*k4+2)*HH], u3 = wu[(4*k4+3)*HH];
        #pragma unroll
        for (int e = 0; e < TE; e++) {
            float4 f = *(const float4*)(sm + e*HH + 4*k4);
            accP[e] = fmaf(f.w, t3, fmaf(f.z, t2, fmaf(f.y, t1, fmaf(f.x, t0, accP[e]))));
            accQ[e] = fmaf(f.w, q3, fmaf(f.z, q2, fmaf(f.y, q1, fmaf(f.x, q0, accQ[e]))));
            accU[e] = fmaf(f.w, u3, fmaf(f.z, u2, fmaf(f.y, u1, fmaf(f.x, u0, accU[e]))));
        }
    }
    #pragma unroll
    for (int e = 0; e < TE; e++) {
        g_P0[(r0 + e)*HH + tid] = accP[e];
        g_Q0[(r0 + e)*HH + tid] = accQ[e];
        g_U0[(r0 + e)*HH + tid] = accU[e];
    }
}

// ---------------- layer-0 gather aggregation (block = dst node) -------------
// sync-free: dpos = sum_w sum_e dvec_e * coef_w(e); one block reduce at end
__global__ void __launch_bounds__(256) agg0_gather(
    const float* __restrict__ Wm, const float* __restrict__ bm,
    const float* __restrict__ Wp)
{
    __shared__ float sred[8][3];
    int d = blockIdx.x, tid = threadIdx.x;
    int lo = g_off[d], hi = g_off[d+1];
    float pdx = g_pos[d*3+0], pdy = g_pos[d*3+1], pdz = g_pos[d*3+2];
    float wd = Wm[(size_t)512*HH + tid];
    float bj = bm[tid];
    float wp = Wp[tid];
    int bt = d >> 11, nt = d & (NPTS-1);
    float q = g_Q0[bt*HH + tid] + g_Q0[(BB + nt)*HH + tid];
    float a = 0.f, cx = 0.f, cy = 0.f, cz = 0.f;
    int lane = tid & 31, wrp = tid >> 5;

    for (int j = lo; j < hi; j++) {
        int s = g_csr[j];
        float dx = g_pos[s*3+0] - pdx;
        float dy = g_pos[s*3+1] - pdy;
        float dz = g_pos[s*3+2] - pdz;
        float sd = sqrtf(dx*dx + dy*dy + dz*dz + 1e-12f);
        int bs = s >> 11, ns = s & (NPTS-1);
        float m = g_P0[bs*HH + tid] + g_P0[(BB + ns)*HH + tid] + q;
        m = fmaxf(fmaf(sd, wd, m) + bj, 0.f);
        a += m;
        float v = m * wp;                      // warp-partial coef
        v += __shfl_xor_sync(0xffffffffu, v, 16);
        v += __shfl_xor_sync(0xffffffffu, v, 8);
        v += __shfl_xor_sync(0xffffffffu, v, 4);
        v += __shfl_xor_sync(0xffffffffu, v, 2);
        v += __shfl_xor_sync(0xffffffffu, v, 1);
        cx = fmaf(-dx, v, cx);                 // (pos[dst]-pos[src]) = -dvec
        cy = fmaf(-dy, v, cy);
        cz = fmaf(-dz, v, cz);
    }
    __nv_bfloat16 h = __float2bfloat16(a);
    g_agg_hi[(size_t)d*HH + tid] = h;
    g_agg_lo[(size_t)d*HH + tid] = __float2bfloat16(a - __bfloat162float(h));

    if (lane == 0) { sred[wrp][0] = cx; sred[wrp][1] = cy; sred[wrp][2] = cz; }
    __syncthreads();
    if (tid < 3) {
        float s = 0.f;
        #pragma unroll
        for (int w = 0; w < 8; w++) s += sred[w][tid];
        g_dpos[d*3 + tid] = s;
    }
}

// ---------------- layer-1 gather aggregation (no dpos) ----------------------
__global__ void __launch_bounds__(256) agg1_gather(
    const float* __restrict__ Wm, const float* __restrict__ bm)
{
    int d = blockIdx.x, tid = threadIdx.x;
    int lo = g_off[d], hi = g_off[d+1];
    float pdx = g_pos[d*3+0], pdy = g_pos[d*3+1], pdz = g_pos[d*3+2];
    float wd = Wm[(size_t)512*HH + tid];
    float bj = bm[tid];
    float q = g_PQ[(size_t)d*512 + 256 + tid];
    float a = 0.f;

    for (int j = lo; j < hi; j++) {
        int s = g_csr[j];
        float dx = g_pos[s*3+0] - pdx;
        float dy = g_pos[s*3+1] - pdy;
        float dz = g_pos[s*3+2] - pdz;
        float sd = sqrtf(dx*dx + dy*dy + dz*dz + 1e-12f);
        float m = fmaf(sd, wd, g_PQ[(size_t)s*512 + tid] + q) + bj;
        a += fmaxf(m, 0.f);
    }
    __nv_bfloat16 h = __float2bfloat16(a);
    g_agg_hi[(size_t)d*HH + tid] = h;
    g_agg_lo[(size_t)d*HH + tid] = __float2bfloat16(a - __bfloat162float(h));
}

// ---------------- upd0 (MMA): h = h0[b]+g[n] + relu(agg@Wu_bot + U0 + bu) ---
__global__ void __launch_bounds__(256) upd0_mma(const float* __restrict__ bu)
{
    __shared__ __align__(16) __nv_bfloat16 sAh[BM*KPAD], sAl[BM*KPAD];
    __shared__ __align__(16) __nv_bfloat16 sBh[BN*KPAD], sBl[BN*KPAD];
    float acc[2][8][4];
    #pragma unroll
    for (int a = 0; a < 2; a++)
        #pragma unroll
        for (int b = 0; b < 8; b++)
            #pragma unroll
            for (int c = 0; c < 4; c++) acc[a][b][c] = 0.f;

    int m0 = blockIdx.x * BM;
    int n0 = blockIdx.y * BN;
    gemm_tile_bf16(g_agg_hi, g_agg_lo, g_agg_hi, g_agg_lo, HH, HH,
                   g_Bu0_hi, g_Bu0_lo, m0, n0, sAh, sAl, sBh, sBl, acc);

    int lane = threadIdx.x & 31, warp = threadIdx.x >> 5;
    int g = lane >> 2, tg = lane & 3;
    int wM = warp >> 1, wN = warp & 1;
    int b = m0 >> 11;
    #pragma unroll
    for (int fm = 0; fm < 2; fm++) {
        #pragma unroll
        for (int fn = 0; fn < 8; fn++) {
            int c = n0 + wN*64 + fn*8 + tg*2;
            float b0 = bu[c], b1 = bu[c+1];
            #pragma unroll
            for (int rr = 0; rr < 2; rr++) {
                int m = m0 + wM*32 + fm*16 + g + rr*8;
                int n = m & (NPTS-1);
                float base0 = g_h0[b*HH + c]   + g_g[n*HH + c];
                float base1 = g_h0[b*HH + c+1] + g_g[n*HH + c+1];
                float ua0 = acc[fm][fn][rr*2+0] + g_U0[b*HH + c]   + g_U0[(BB+n)*HH + c]   + b0;
                float ua1 = acc[fm][fn][rr*2+1] + g_U0[b*HH + c+1] + g_U0[(BB+n)*HH + c+1] + b1;
                float o0 = base0 + fmaxf(ua0, 0.f);
                float o1 = base1 + fmaxf(ua1, 0.f);
                __nv_bfloat16 h0_ = __float2bfloat16(o0);
                __nv_bfloat16 h1_ = __float2bfloat16(o1);
                *(unsigned*)(g_h_hi + (size_t)m*HH + c) = pack_bf2(h0_, h1_);
                *(unsigned*)(g_h_lo + (size_t)m*HH + c) =
                    pack_bf2(__float2bfloat16(o0 - __bfloat162float(h0_)),
                             __float2bfloat16(o1 - __bfloat162float(h1_)));
            }
        }
    }
}

// ---------------- pq1 (MMA): g_PQ = h @ [Wm_top | Wm_mid] -------------------
__global__ void __launch_bounds__(256) pq1_mma()
{
    __shared__ __align__(16) __nv_bfloat16 sAh[BM*KPAD], sAl[BM*KPAD];
    __shared__ __align__(16) __nv_bfloat16 sBh[BN*KPAD], sBl[BN*KPAD];
    float acc[2][8][4];
    #pragma unroll
    for (int a = 0; a < 2; a++)
        #pragma unroll
        for (int b = 0; b < 8; b++)
            #pragma unroll
            for (int c = 0; c < 4; c++) acc[a][b][c] = 0.f;

    int m0 = blockIdx.x * BM;
    int n0 = blockIdx.y * BN;
    gemm_tile_bf16(g_h_hi, g_h_lo, g_h_hi, g_h_lo, HH, HH,
                   g_Bpq_hi, g_Bpq_lo, m0, n0, sAh, sAl, sBh, sBl, acc);

    int lane = threadIdx.x & 31, warp = threadIdx.x >> 5;
    int g = lane >> 2, tg = lane & 3;
    int wM = warp >> 1, wN = warp & 1;
    #pragma unroll
    for (int fm = 0; fm < 2; fm++) {
        #pragma unroll
        for (int fn = 0; fn < 8; fn++) {
            int c = n0 + wN*64 + fn*8 + tg*2;
            #pragma unroll
            for (int rr = 0; rr < 2; rr++) {
                int m = m0 + wM*32 + fm*16 + g + rr*8;
                float2 o; o.x = acc[fm][fn][rr*2+0]; o.y = acc[fm][fn][rr*2+1];
                *(float2*)(g_PQ + (size_t)m*512 + c) = o;
            }
        }
    }
}

// ---------------- upd1 (MMA) + fused output ---------------------------------
__global__ void __launch_bounds__(256) upd1_mma(
    const float* __restrict__ bu, const float* __restrict__ Wo,
    float* __restrict__ out)
{
    __shared__ __align__(16) __nv_bfloat16 sAh[BM*KPAD], sAl[BM*KPAD];
    __shared__ __align__(16) __nv_bfloat16 sBh[BN*KPAD], sBl[BN*KPAD];
    float acc[2][8][4];
    #pragma unroll
    for (int a = 0; a < 2; a++)
        #pragma unroll
        for (int b = 0; b < 8; b++)
            #pragma unroll
            for (int c = 0; c < 4; c++) acc[a][b][c] = 0.f;

    int m0 = blockIdx.x * BM;
    int n0 = blockIdx.y * BN;
    gemm_tile_bf16(g_h_hi, g_h_lo, g_agg_hi, g_agg_lo, HH, 2*HH,
                   g_Bu1_hi, g_Bu1_lo, m0, n0, sAh, sAl, sBh, sBl, acc);

    int lane = threadIdx.x & 31, warp = threadIdx.x >> 5;
    int g = lane >> 2, tg = lane & 3;
    int wM = warp >> 1, wN = warp & 1;
    #pragma unroll
    for (int fm = 0; fm < 2; fm++) {
        #pragma unroll
        for (int rr = 0; rr < 2; rr++) {
            int m = m0 + wM*32 + fm*16 + g + rr*8;
            float rowsum = 0.f;
            #pragma unroll
            for (int fn = 0; fn < 8; fn++) {
                int c = n0 + wN*64 + fn*8 + tg*2;
                unsigned hh = *(const unsigned*)(g_h_hi + (size_t)m*HH + c);
                unsigned hl = *(const unsigned*)(g_h_lo + (size_t)m*HH + c);
                float hold0 = __bfloat162float(__ushort_as_bfloat16((unsigned short)(hh & 0xffff)))
                            + __bfloat162float(__ushort_as_bfloat16((unsigned short)(hl & 0xffff)));
                float hold1 = __bfloat162float(__ushort_as_bfloat16((unsigned short)(hh >> 16)))
                            + __bfloat162float(__ushort_as_bfloat16((unsigned short)(hl >> 16)));
                float o0 = hold0 + fmaxf(acc[fm][fn][rr*2+0] + bu[c], 0.f);
                float o1 = hold1 + fmaxf(acc[fm][fn][rr*2+1] + bu[c+1], 0.f);
                rowsum = fmaf(o0, Wo[c], rowsum);
                rowsum = fmaf(o1, Wo[c+1], rowsum);
            }
            rowsum += __shfl_xor_sync(0xffffffffu, rowsum, 1);
            rowsum += __shfl_xor_sync(0xffffffffu, rowsum, 2);
            if (tg == 0) atomicAdd(out + m, rowsum);
        }
    }
}

// ---------------------------------------------------------------------------
extern "C" void kernel_launch(void* const* d_in, const int* in_sizes, int n_in,
                              void* d_out, int out_size)
{
    const float* x         = (const float*)d_in[0];
    const float* positions = (const float*)d_in[1];
    const float* W_in      = (const float*)d_in[2];
    const float* b_in      = (const float*)d_in[3];
    const float* Wg1       = (const float*)d_in[4];
    const float* bg1       = (const float*)d_in[5];
    const float* Wg2       = (const float*)d_in[6];
    const float* bg2       = (const float*)d_in[7];
    const float* Wm        = (const float*)d_in[8];
    const float* bm        = (const float*)d_in[9];
    const float* Wu        = (const float*)d_in[10];
    const float* bu        = (const float*)d_in[11];
    const float* Wp        = (const float*)d_in[12];
    const float* W_out     = (const float*)d_in[13];
    const float* b_out     = (const float*)d_in[14];
    const int*   edge      = (const int*)d_in[15];
    float* out = (float*)d_out;

    const int* srcp = edge;
    const int* dstp = edge + NE;
    const float* Wm1 = Wm + (size_t)513*HH;
    const float* Wu1 = Wu + (size_t)512*HH;

    // front-end + weight prep + CSR
    k_h0<<<BB, 256>>>(x, W_in, b_in);
    k_meand<<<NPTS, 256>>>(positions);
    k_geo<<<NPTS, 256>>>(Wg1, bg1, Wg2, bg2);
    k_posinit<<<(NN*SD + 255)/256, 256>>>(positions);
    k_prep_pq<<<512, 256>>>(Wm1);
    k_prep_u1<<<512, 256>>>(Wu1);
    k_prep_u0<<<256, 256>>>(Wu);
    k_degzero<<<NN/256, 256>>>();
    k_hist<<<NE/256, 256>>>(dstp);
    k_scan<<<1, 1024>>>();
    k_scatter<<<NE/256, 256>>>(srcp, dstp);

    // ---- layer 0 ----
    pq0_kernel<<<R0/TE, 256>>>(Wm, Wu);
    agg0_gather<<<NN, 256>>>(Wm, bm, Wp);
    upd0_mma<<<dim3(NN/BM, HH/BN), 256>>>(bu);
    k_posupd<<<(NN*SD + 255)/256, 256>>>();

    // ---- layer 1 ----
    pq1_mma<<<dim3(NN/BM, 512/BN), 256>>>();
    agg1_gather<<<NN, 256>>>(Wm1, bm + HH);
    k_oinit<<<NN/256, 256>>>(b_out, out);
    upd1_mma<<<dim3(NN/BM, HH/BN), 256>>>(bu + HH, W_out, out);
}